// round 1
// baseline (speedup 1.0000x reference)
#include <cuda_runtime.h>
#include <cuda_bf16.h>
#include <math.h>

// Problem constants (fixed shapes for RoIPointPool3d_23845658427905)
#define BB   4
#define NPTS 16384
#define MM   128
#define CF   128
#define SS   512
#define OUTF (3 + CF)   // 131 floats per pooled row

// Scratch (device globals — no allocation allowed)
__device__ int g_table[BB * MM * SS];   // first min(cnt,S) in-box point indices per box
__device__ int g_cnt[BB * MM];          // in-box counts (capped semantics: >=S means "use s directly")

// ---------------------------------------------------------------------------
// Kernel 1: per-box membership test + ordered compaction of in-box indices.
// One CTA per (b, m) box. 512 threads, 32 chunks of 512 points each.
// Ordering preserved: chunk-serial outer loop, ballot+warp-scan inner order.
// ---------------------------------------------------------------------------
__global__ __launch_bounds__(512) void roipool_mask_kernel(
    const float* __restrict__ points,   // (B, N, 3)
    const float* __restrict__ boxes,    // (B, M, 7)
    float* __restrict__ flags)          // (B, M) empty flags as float 0/1
{
    const int bm = blockIdx.x;          // 0 .. B*M-1
    const int b  = bm / MM;

    __shared__ float sbox[7];
    __shared__ float scos, ssin;
    __shared__ int   warpCnt[16];
    __shared__ int   total;

    const int tid  = threadIdx.x;
    const int lane = tid & 31;
    const int warp = tid >> 5;

    if (tid < 7) sbox[tid] = boxes[bm * 7 + tid];
    if (tid == 0) total = 0;
    __syncthreads();
    if (tid == 0) {
        // double-precision sincos -> correctly-rounded f32, fast-math immune
        double mrz = -(double)sbox[6];
        scos = (float)cos(mrz);
        ssin = (float)sin(mrz);
    }
    __syncthreads();

    const float cx = sbox[0], cy = sbox[1];
    const float dz = sbox[5];
    const float cz = __fadd_rn(sbox[2], __fmul_rn(0.5f, dz)); // bottom -> center
    const float hx = __fmul_rn(0.5f, sbox[3]);
    const float hy = __fmul_rn(0.5f, sbox[4]);
    const float hz = __fmul_rn(0.5f, dz);
    const float ca = scos, sa = ssin;

    const float* pbase = points + (size_t)b * NPTS * 3;

    for (int c0 = 0; c0 < NPTS; c0 += 512) {
        const int p = c0 + tid;
        const float x = pbase[p * 3 + 0];
        const float y = pbase[p * 3 + 1];
        const float z = pbase[p * 3 + 2];

        // Exact op sequence matching XLA (no FMA contraction):
        const float sx = __fsub_rn(x, cx);
        const float sy = __fsub_rn(y, cy);
        const float lx = __fsub_rn(__fmul_rn(sx, ca), __fmul_rn(sy, sa));
        const float ly = __fadd_rn(__fmul_rn(sx, sa), __fmul_rn(sy, ca));

        const bool m = (fabsf(__fsub_rn(z, cz)) <= hz)
                     && (lx > -hx) && (lx < hx)
                     && (ly > -hy) && (ly < hy);

        const unsigned ball = __ballot_sync(0xffffffffu, m);
        if (lane == 0) warpCnt[warp] = __popc(ball);
        __syncthreads();

        // position of this point among in-box points (first-come order)
        int basew = total;
        #pragma unroll
        for (int w = 0; w < 16; w++)
            if (w < warp) basew += warpCnt[w];
        const int pos = basew + __popc(ball & ((1u << lane) - 1));
        if (m && pos < SS) g_table[bm * SS + pos] = p;

        int newtot = 0;
        if (tid == 0) {
            newtot = total;
            #pragma unroll
            for (int w = 0; w < 16; w++) newtot += warpCnt[w];
        }
        __syncthreads();              // everyone done reading total/warpCnt
        if (tid == 0) total = newtot; // safe: next read of total is after next barrier
    }
    __syncthreads();

    if (tid == 0) {
        g_cnt[bm] = total;
        flags[bm] = (total == 0) ? 1.0f : 0.0f;
    }
}

// ---------------------------------------------------------------------------
// Kernel 2: gather pooled rows. One warp per output row (b, m, s).
// Row = [points[idx] (3) | feats[idx] (128)], zeros if box empty.
// ---------------------------------------------------------------------------
__global__ __launch_bounds__(256) void roipool_gather_kernel(
    const float* __restrict__ points,   // (B, N, 3)
    const float* __restrict__ feats,    // (B, N, C)
    float* __restrict__ out)            // (B, M, S, 131)
{
    const int warpGlobal = (int)((blockIdx.x * blockDim.x + threadIdx.x) >> 5);
    const int lane = threadIdx.x & 31;
    if (warpGlobal >= BB * MM * SS) return;

    const int s  = warpGlobal % SS;
    const int bm = warpGlobal / SS;
    const int b  = bm / MM;

    const int cnt = g_cnt[bm];
    float* orow = out + (size_t)warpGlobal * OUTF;

    if (cnt == 0) {
        #pragma unroll
        for (int e = lane; e < OUTF; e += 32) orow[e] = 0.0f;
        return;
    }

    // wrap-around duplication: idx = table[s % cnt]; for cnt>=S, s%cnt==s.
    const int j   = (cnt >= SS) ? s : (s % cnt);
    const int idx = g_table[bm * SS + j];

    const float* prow = points + ((size_t)b * NPTS + idx) * 3;
    const float* frow = feats  + ((size_t)b * NPTS + idx) * CF;

    #pragma unroll
    for (int e = lane; e < OUTF; e += 32)
        orow[e] = (e < 3) ? prow[e] : frow[e - 3];
}

// ---------------------------------------------------------------------------
extern "C" void kernel_launch(void* const* d_in, const int* in_sizes, int n_in,
                              void* d_out, int out_size)
{
    const float* points = (const float*)d_in[0];   // (B, N, 3)
    const float* feats  = (const float*)d_in[1];   // (B, N, C)
    const float* boxes  = (const float*)d_in[2];   // (B, M, 7)

    float* out   = (float*)d_out;
    float* flags = out + (size_t)BB * MM * SS * OUTF;  // empty flags appended

    // Phase 1: membership + ordered index tables (+ empty flags)
    roipool_mask_kernel<<<BB * MM, 512>>>(points, boxes, flags);

    // Phase 2: gather pooled rows (one warp per row)
    const int rows = BB * MM * SS;             // 262144 rows
    const int warpsPerBlock = 256 / 32;        // 8
    const int grid = (rows + warpsPerBlock - 1) / warpsPerBlock;  // 32768
    roipool_gather_kernel<<<grid, 256>>>(points, feats, out);
}

// round 2
// speedup vs baseline: 1.7099x; 1.7099x over previous
#include <cuda_runtime.h>
#include <cuda_bf16.h>
#include <math.h>

// Problem constants (fixed shapes for RoIPointPool3d_23845658427905)
#define BB   4
#define NPTS 16384
#define MM   128
#define CF   128
#define SS   512
#define OUTF (3 + CF)   // 131 floats per pooled row
#define BPC  4          // boxes per CTA in the mask kernel (MM % BPC == 0)

// Scratch (device globals — no allocation allowed)
__device__ int g_table[BB * MM * SS];   // first min(cnt,S) in-box point indices per box
__device__ int g_cnt[BB * MM];          // in-box counts

// ---------------------------------------------------------------------------
// Kernel 1: membership + ordered compaction, barrier-light two-phase ballots.
// Grid: (B*M)/BPC CTAs, 512 threads (16 warps). Each warp owns 1024 consecutive
// points and tests them against BPC boxes. Ballot words are stored to smem
// (phase B, no block barriers), then after ONE __syncthreads each warp replays
// its ballots with its exclusive prefix base to emit ordered table entries.
// ---------------------------------------------------------------------------
__global__ __launch_bounds__(512) void roipool_mask_kernel(
    const float* __restrict__ points,   // (B, N, 3)
    const float* __restrict__ boxes,    // (B, M, 7)
    float* __restrict__ flags)          // (B, M) empty flags as float 0/1
{
    const int bm0 = blockIdx.x * BPC;     // first box of this CTA
    const int b   = bm0 / MM;             // batch (all BPC boxes same batch)

    __shared__ float    raw[BPC][7];
    __shared__ float    sb[BPC][8];       // cx, cy, czc, hx, hy, hz, ca, sa
    __shared__ unsigned sball[BPC][16][32];
    __shared__ int      wtot[BPC][16];

    const int tid  = threadIdx.x;
    const int lane = tid & 31;
    const int w    = tid >> 5;

    if (tid < BPC * 7) raw[tid / 7][tid % 7] = boxes[bm0 * 7 + tid];
    __syncthreads();
    if (tid < BPC) {
        const int q = tid;
        sb[q][0] = raw[q][0];                                      // cx
        sb[q][1] = raw[q][1];                                      // cy
        sb[q][2] = __fadd_rn(raw[q][2], __fmul_rn(0.5f, raw[q][5])); // cz center
        sb[q][3] = __fmul_rn(0.5f, raw[q][3]);                     // hx
        sb[q][4] = __fmul_rn(0.5f, raw[q][4]);                     // hy
        sb[q][5] = __fmul_rn(0.5f, raw[q][5]);                     // hz
        double mrz = -(double)raw[q][6];
        sb[q][6] = (float)cos(mrz);                                // ca (fast-math immune)
        sb[q][7] = (float)sin(mrz);                                // sa
    }
    __syncthreads();

    // box params into registers
    float cx[BPC], cy[BPC], cz[BPC], hx[BPC], hy[BPC], hz[BPC], ca[BPC], sa[BPC];
    #pragma unroll
    for (int q = 0; q < BPC; q++) {
        cx[q] = sb[q][0]; cy[q] = sb[q][1]; cz[q] = sb[q][2];
        hx[q] = sb[q][3]; hy[q] = sb[q][4]; hz[q] = sb[q][5];
        ca[q] = sb[q][6]; sa[q] = sb[q][7];
    }

    // Phase B: ballots, no block barriers (full load MLP within each warp)
    const float* pb = points + ((size_t)b * NPTS + (size_t)w * 1024) * 3;
    int cnt[BPC];
    #pragma unroll
    for (int q = 0; q < BPC; q++) cnt[q] = 0;

    #pragma unroll 4
    for (int j = 0; j < 32; j++) {
        const int i3 = (j * 32 + lane) * 3;
        const float x = pb[i3 + 0];
        const float y = pb[i3 + 1];
        const float z = pb[i3 + 2];
        #pragma unroll
        for (int q = 0; q < BPC; q++) {
            const float sx = __fsub_rn(x, cx[q]);
            const float sy = __fsub_rn(y, cy[q]);
            const float lx = __fsub_rn(__fmul_rn(sx, ca[q]), __fmul_rn(sy, sa[q]));
            const float ly = __fadd_rn(__fmul_rn(sx, sa[q]), __fmul_rn(sy, ca[q]));
            const bool m = (fabsf(__fsub_rn(z, cz[q])) <= hz[q])
                         && (lx > -hx[q]) && (lx < hx[q])
                         && (ly > -hy[q]) && (ly < hy[q]);
            const unsigned ball = __ballot_sync(0xffffffffu, m);
            if (lane == 0) sball[q][w][j] = ball;
            cnt[q] += __popc(ball);
        }
    }
    if (lane == 0) {
        #pragma unroll
        for (int q = 0; q < BPC; q++) wtot[q][w] = cnt[q];
    }
    __syncthreads();

    // Phase D: replay ballots with exclusive warp base (all smem, fast)
    #pragma unroll
    for (int q = 0; q < BPC; q++) {
        int base = 0;
        #pragma unroll
        for (int v = 0; v < 16; v++)
            if (v < w) base += wtot[q][v];
        int run = base;
        int* tbl = g_table + (size_t)(bm0 + q) * SS;
        const unsigned lt = (1u << lane) - 1u;
        for (int j = 0; j < 32; j++) {
            const unsigned ball = sball[q][w][j];
            if (ball) {
                const int pre = __popc(ball & lt);
                if (((ball >> lane) & 1u) && (run + pre) < SS)
                    tbl[run + pre] = w * 1024 + j * 32 + lane;
                run += __popc(ball);
            }
        }
    }

    if (tid < BPC) {
        int tot = 0;
        #pragma unroll
        for (int v = 0; v < 16; v++) tot += wtot[tid][v];
        g_cnt[bm0 + tid] = tot;
        flags[bm0 + tid] = (tot == 0) ? 1.0f : 0.0f;
    }
}

// ---------------------------------------------------------------------------
// Kernel 2: gather pooled rows. One CTA per box (512 threads, 16 warps).
// Index table resolved once into smem (kills the global dependent chain);
// each warp handles 32 rows, 2 rows per iteration for MLP.
// ---------------------------------------------------------------------------
__global__ __launch_bounds__(512) void roipool_gather_kernel(
    const float* __restrict__ points,   // (B, N, 3)
    const float* __restrict__ feats,    // (B, N, C)
    float* __restrict__ out)            // (B, M, S, 131)
{
    const int bm = blockIdx.x;
    const int b  = bm / MM;
    const int tid  = threadIdx.x;
    const int lane = tid & 31;
    const int w    = tid >> 5;

    __shared__ int sidx[SS];
    __shared__ int scnt;

    if (tid == 0) scnt = g_cnt[bm];
    __syncthreads();
    const int cnt = scnt;

    float* obox = out + (size_t)bm * SS * OUTF;

    if (cnt == 0) {
        // zero the whole box slab (16B-aligned: 512*131*4 bytes, start multiple of 16)
        float4 zz = make_float4(0.f, 0.f, 0.f, 0.f);
        float4* o4 = (float4*)obox;
        const int n4 = SS * OUTF / 4;                 // 67072/4 = 16768
        for (int i = tid; i < n4; i += 512) o4[i] = zz;
        return;
    }

    // resolve wrap-around indices once (s % cnt == s when cnt >= SS)
    {
        const int s = tid;                            // SS == blockDim
        sidx[s] = g_table[(size_t)bm * SS + (s % cnt)];
    }
    __syncthreads();

    const float* pbat = points + (size_t)b * NPTS * 3;
    const float* fbat = feats  + (size_t)b * NPTS * CF;

    // each warp: rows s = w, w+16, ..., two rows per iteration
    for (int s = w; s < SS; s += 32) {
        const int s2  = s + 16;
        const int ia  = sidx[s];
        const int ib  = sidx[s2];
        const float* fa = fbat + (size_t)ia * CF;
        const float* fb = fbat + (size_t)ib * CF;
        const float* pa = pbat + (size_t)ia * 3;
        const float* pb = pbat + (size_t)ib * 3;
        float* oa = obox + (size_t)s  * OUTF;
        float* ob = obox + (size_t)s2 * OUTF;

        // row A loads (e = lane + 32k), coalesced
        const float a0 = (lane < 3) ? pa[lane] : fa[lane - 3];
        const float a1 = fa[lane + 29];
        const float a2 = fa[lane + 61];
        const float a3 = fa[lane + 93];
        float a4 = 0.f; if (lane < 3) a4 = fa[lane + 125];
        // row B loads
        const float b0 = (lane < 3) ? pb[lane] : fb[lane - 3];
        const float b1 = fb[lane + 29];
        const float b2 = fb[lane + 61];
        const float b3 = fb[lane + 93];
        float b4 = 0.f; if (lane < 3) b4 = fb[lane + 125];

        oa[lane]       = a0;
        oa[lane + 32]  = a1;
        oa[lane + 64]  = a2;
        oa[lane + 96]  = a3;
        if (lane < 3) oa[lane + 128] = a4;
        ob[lane]       = b0;
        ob[lane + 32]  = b1;
        ob[lane + 64]  = b2;
        ob[lane + 96]  = b3;
        if (lane < 3) ob[lane + 128] = b4;
    }
}

// ---------------------------------------------------------------------------
extern "C" void kernel_launch(void* const* d_in, const int* in_sizes, int n_in,
                              void* d_out, int out_size)
{
    const float* points = (const float*)d_in[0];   // (B, N, 3)
    const float* feats  = (const float*)d_in[1];   // (B, N, C)
    const float* boxes  = (const float*)d_in[2];   // (B, M, 7)

    float* out   = (float*)d_out;
    float* flags = out + (size_t)BB * MM * SS * OUTF;  // empty flags appended

    roipool_mask_kernel<<<(BB * MM) / BPC, 512>>>(points, boxes, flags);
    roipool_gather_kernel<<<BB * MM, 512>>>(points, feats, out);
}

// round 3
// speedup vs baseline: 2.1716x; 1.2700x over previous
#include <cuda_runtime.h>
#include <cuda_bf16.h>
#include <math.h>

// Problem constants (fixed shapes for RoIPointPool3d_23845658427905)
#define BB   4
#define NPTS 16384
#define MM   128
#define CF   128
#define SS   512
#define OUTF (3 + CF)   // 131 floats per pooled row
#define BPC  4          // boxes per mask CTA
#define PSPL 4          // point-range splits per box group
#define PPS  (NPTS / PSPL)   // 4096 points per split

// Scratch (device globals — no allocation allowed)
__device__ int   g_table[BB * MM * PSPL * SS]; // per (box, split): ordered in-box point indices
__device__ int   g_cnt[BB * MM * PSPL];        // per (box, split): full in-box counts
__device__ float g_prep[BB * MM * 8];          // cx, cy, czc, hx, hy, hz, ca, sa

// ---------------------------------------------------------------------------
// Kernel 0: box preprocessing (incl. fp64 trig, fast-math immune) — one
// thread per box so the slow fp64 chains run fully in parallel and never
// stall the mask CTAs.
// ---------------------------------------------------------------------------
__global__ __launch_bounds__(32) void roipool_prep_kernel(
    const float* __restrict__ boxes)    // (B, M, 7)
{
    const int i = blockIdx.x * 32 + threadIdx.x;   // 0..511
    const float r0 = boxes[i * 7 + 0];
    const float r1 = boxes[i * 7 + 1];
    const float r2 = boxes[i * 7 + 2];
    const float r3 = boxes[i * 7 + 3];
    const float r4 = boxes[i * 7 + 4];
    const float r5 = boxes[i * 7 + 5];
    const float r6 = boxes[i * 7 + 6];

    const double mrz = -(double)r6;
    float* o = g_prep + i * 8;
    o[0] = r0;                                        // cx
    o[1] = r1;                                        // cy
    o[2] = __fadd_rn(r2, __fmul_rn(0.5f, r5));        // cz (bottom -> center)
    o[3] = __fmul_rn(0.5f, r3);                       // hx
    o[4] = __fmul_rn(0.5f, r4);                       // hy
    o[5] = __fmul_rn(0.5f, r5);                       // hz
    o[6] = (float)cos(mrz);                           // ca
    o[7] = (float)sin(mrz);                           // sa
}

// ---------------------------------------------------------------------------
// Kernel 1: membership + ordered compaction.
// Grid: 128 box-quads x 4 point-splits = 512 CTAs, 512 threads.
// Each warp owns 256 consecutive points of its split (8 ballot words),
// tests them against 4 boxes; one __syncthreads, then ballots are replayed
// with exclusive warp prefixes to emit ordered per-(box,split) tables.
// ---------------------------------------------------------------------------
__global__ __launch_bounds__(512, 2) void roipool_mask_kernel(
    const float* __restrict__ points)   // (B, N, 3)
{
    const int split = blockIdx.x & (PSPL - 1);
    const int quad  = blockIdx.x >> 2;       // 0..127
    const int bm0   = quad * BPC;            // first box of the quad
    const int b     = bm0 >> 7;              // / MM

    __shared__ float    sprep[BPC * 8];
    __shared__ unsigned sball[BPC][16][8];
    __shared__ int      wtot[BPC][16];

    const int tid  = threadIdx.x;
    const int lane = tid & 31;
    const int w    = tid >> 5;

    if (tid < BPC * 8) sprep[tid] = g_prep[bm0 * 8 + tid];
    __syncthreads();

    float cx[BPC], cy[BPC], cz[BPC], hx[BPC], hy[BPC], hz[BPC], ca[BPC], sa[BPC];
    #pragma unroll
    for (int q = 0; q < BPC; q++) {
        cx[q] = sprep[q * 8 + 0]; cy[q] = sprep[q * 8 + 1];
        cz[q] = sprep[q * 8 + 2]; hx[q] = sprep[q * 8 + 3];
        hy[q] = sprep[q * 8 + 4]; hz[q] = sprep[q * 8 + 5];
        ca[q] = sprep[q * 8 + 6]; sa[q] = sprep[q * 8 + 7];
    }

    // this warp's point range: 256 points
    const int base_local = split * PPS + w * 256;          // batch-relative
    const float* pb = points + ((size_t)b * NPTS + base_local) * 3;

    int cnt[BPC];
    #pragma unroll
    for (int q = 0; q < BPC; q++) cnt[q] = 0;

    for (int j = 0; j < 8; j++) {
        const int i3 = (j * 32 + lane) * 3;
        const float x = pb[i3 + 0];
        const float y = pb[i3 + 1];
        const float z = pb[i3 + 2];
        #pragma unroll
        for (int q = 0; q < BPC; q++) {
            const float sx = __fsub_rn(x, cx[q]);
            const float sy = __fsub_rn(y, cy[q]);
            const float lx = __fsub_rn(__fmul_rn(sx, ca[q]), __fmul_rn(sy, sa[q]));
            const float ly = __fadd_rn(__fmul_rn(sx, sa[q]), __fmul_rn(sy, ca[q]));
            const float zd = __fsub_rn(z, cz[q]);
            // |lx|<hx  <=>  (lx>-hx && lx<hx) exactly (hx>0; NaN -> false)
            const bool m = (fabsf(zd) <= hz[q]) && (fabsf(lx) < hx[q]) && (fabsf(ly) < hy[q]);
            const unsigned ball = __ballot_sync(0xffffffffu, m);
            if (lane == 0) sball[q][w][j] = ball;
            cnt[q] += __popc(ball);
        }
    }
    if (lane == 0) {
        #pragma unroll
        for (int q = 0; q < BPC; q++) wtot[q][w] = cnt[q];
    }
    __syncthreads();

    // replay ballots with exclusive warp base -> ordered table entries
    const unsigned lt = (1u << lane) - 1u;
    #pragma unroll
    for (int q = 0; q < BPC; q++) {
        int run = 0;
        #pragma unroll
        for (int v = 0; v < 16; v++)
            if (v < w) run += wtot[q][v];
        int* tbl = g_table + (size_t)((bm0 + q) * PSPL + split) * SS;
        #pragma unroll
        for (int j = 0; j < 8; j++) {
            const unsigned ball = sball[q][w][j];
            const int pre = __popc(ball & lt);
            if (((ball >> lane) & 1u) && (run + pre) < SS)
                tbl[run + pre] = base_local + j * 32 + lane;
            run += __popc(ball);
        }
    }

    if (tid < BPC) {
        int tot = 0;
        #pragma unroll
        for (int v = 0; v < 16; v++) tot += wtot[tid][v];
        g_cnt[(bm0 + tid) * PSPL + split] = tot;
    }
}

// ---------------------------------------------------------------------------
// Kernel 2: gather pooled rows. One CTA per box (512 threads, 16 warps).
// Resolves wrap-around indices across the 4 split tables once into smem,
// then each warp emits 32 consecutive rows, 4 rows per iteration, with
// streaming stores (output is write-once, never re-read on device).
// ---------------------------------------------------------------------------
__global__ __launch_bounds__(512, 2) void roipool_gather_kernel(
    const float* __restrict__ points,   // (B, N, 3)
    const float* __restrict__ feats,    // (B, N, C)
    float* __restrict__ out,            // (B, M, S, 131)
    float* __restrict__ flags)          // (B, M)
{
    const int bm = blockIdx.x;
    const int b  = bm >> 7;             // / MM
    const int tid  = threadIdx.x;
    const int lane = tid & 31;
    const int w    = tid >> 5;

    __shared__ int sidx[SS];
    __shared__ int pf[4];               // exclusive prefix of the 4 split counts
    __shared__ int scnt;

    if (tid == 0) {
        const int c0 = g_cnt[bm * PSPL + 0];
        const int c1 = g_cnt[bm * PSPL + 1];
        const int c2 = g_cnt[bm * PSPL + 2];
        const int c3 = g_cnt[bm * PSPL + 3];
        pf[0] = 0; pf[1] = c0; pf[2] = c0 + c1; pf[3] = c0 + c1 + c2;
        const int tot = c0 + c1 + c2 + c3;
        scnt = tot;
        flags[bm] = (tot == 0) ? 1.0f : 0.0f;
    }
    __syncthreads();
    const int cnt = scnt;

    float* obox = out + (size_t)bm * SS * OUTF;

    if (cnt == 0) {
        const float4 zz = make_float4(0.f, 0.f, 0.f, 0.f);
        float4* o4 = (float4*)obox;
        for (int i = tid; i < SS * OUTF / 4; i += 512) __stcs(&o4[i], zz);
        return;
    }

    // resolve wrap-around index for this thread's row
    {
        const int s = tid;                       // SS == blockDim.x
        const int j = s % cnt;                   // s < 512, cnt >= 1
        const int p = (j >= pf[3]) ? 3 : (j >= pf[2]) ? 2 : (j >= pf[1]) ? 1 : 0;
        sidx[s] = g_table[(size_t)(bm * PSPL + p) * SS + (j - pf[p])];
    }
    __syncthreads();

    const float* pbat = points + (size_t)b * NPTS * 3;
    const float* fbat = feats  + (size_t)b * NPTS * CF;

    // warp w handles rows [32w, 32w+32), 4 rows per iteration
    const int s0 = w * 32;
    for (int i = 0; i < 8; i++) {
        const int s = s0 + i * 4;
        float v[4][5];
        #pragma unroll
        for (int r = 0; r < 4; r++) {
            const int idx = sidx[s + r];
            const float* prow = pbat + (size_t)idx * 3;
            const float* frow = fbat + (size_t)idx * CF;
            v[r][0] = (lane < 3) ? prow[lane] : frow[lane - 3];
            v[r][1] = frow[lane + 29];
            v[r][2] = frow[lane + 61];
            v[r][3] = frow[lane + 93];
            v[r][4] = (lane < 3) ? frow[lane + 125] : 0.0f;
        }
        #pragma unroll
        for (int r = 0; r < 4; r++) {
            float* orow = obox + (size_t)(s + r) * OUTF;
            __stcs(&orow[lane],      v[r][0]);
            __stcs(&orow[lane + 32], v[r][1]);
            __stcs(&orow[lane + 64], v[r][2]);
            __stcs(&orow[lane + 96], v[r][3]);
            if (lane < 3) __stcs(&orow[lane + 128], v[r][4]);
        }
    }
}

// ---------------------------------------------------------------------------
extern "C" void kernel_launch(void* const* d_in, const int* in_sizes, int n_in,
                              void* d_out, int out_size)
{
    const float* points = (const float*)d_in[0];   // (B, N, 3)
    const float* feats  = (const float*)d_in[1];   // (B, N, C)
    const float* boxes  = (const float*)d_in[2];   // (B, M, 7)

    float* out   = (float*)d_out;
    float* flags = out + (size_t)BB * MM * SS * OUTF;  // empty flags appended

    roipool_prep_kernel<<<16, 32>>>(boxes);
    roipool_mask_kernel<<<(BB * MM / BPC) * PSPL, 512>>>(points);
    roipool_gather_kernel<<<BB * MM, 512>>>(points, feats, out, flags);
}

// round 4
// speedup vs baseline: 2.1880x; 1.0075x over previous
#include <cuda_runtime.h>
#include <cuda_bf16.h>
#include <math.h>

// Problem constants (fixed shapes for RoIPointPool3d_23845658427905)
#define BB   4
#define NPTS 16384
#define MM   128
#define CF   128
#define SS   512
#define OUTF (3 + CF)   // 131 floats per pooled row
#define BPC  4          // boxes per mask CTA
#define PSPL 4          // point-range splits per box group
#define PPS  (NPTS / PSPL)   // 4096 points per split

// Scratch (device globals — no allocation allowed)
__device__ int g_table[BB * MM * PSPL * SS]; // per (box, split): ordered in-box indices
__device__ int g_cnt[BB * MM * PSPL];        // per (box, split): in-box counts

// ---------------------------------------------------------------------------
// Kernel 1: fused box-prep (fp64 sincos, fast-math immune) + membership +
// ordered compaction. Grid: 128 box-quads x 4 point-splits = 512 CTAs,
// 512 threads. Lanes 0-3 of warp 0 prep the 4 boxes (one sincos chain each,
// in parallel lanes) while the other warps wait at one barrier; then each
// warp tests its 256 consecutive points against 4 boxes, stores ballot words
// to smem, and after one more barrier replays them with exclusive warp
// prefixes to emit ordered per-(box,split) tables.
// ---------------------------------------------------------------------------
__global__ __launch_bounds__(512) void roipool_mask_kernel(
    const float* __restrict__ points,   // (B, N, 3)
    const float* __restrict__ boxes)    // (B, M, 7)
{
    const int split = blockIdx.x & (PSPL - 1);
    const int quad  = blockIdx.x >> 2;       // 0..127
    const int bm0   = quad * BPC;            // first box of the quad
    const int b     = bm0 >> 7;              // / MM

    __shared__ float    sprep[BPC * 8];      // cx, cy, czc, hx, hy, hz, ca, sa
    __shared__ unsigned sball[BPC][16][8];
    __shared__ int      wtot[BPC][16];

    const int tid  = threadIdx.x;
    const int lane = tid & 31;
    const int w    = tid >> 5;

    if (w == 0 && lane < BPC) {
        const int q = lane;
        const float* bx = boxes + (size_t)(bm0 + q) * 7;
        const float r0 = bx[0], r1 = bx[1], r2 = bx[2];
        const float r3 = bx[3], r4 = bx[4], r5 = bx[5], r6 = bx[6];
        double sv, cv;
        sincos(-(double)r6, &sv, &cv);
        float* o = sprep + q * 8;
        o[0] = r0;
        o[1] = r1;
        o[2] = __fadd_rn(r2, __fmul_rn(0.5f, r5));
        o[3] = __fmul_rn(0.5f, r3);
        o[4] = __fmul_rn(0.5f, r4);
        o[5] = __fmul_rn(0.5f, r5);
        o[6] = (float)cv;
        o[7] = (float)sv;
    }
    __syncthreads();

    float cx[BPC], cy[BPC], cz[BPC], hx[BPC], hy[BPC], hz[BPC], ca[BPC], sa[BPC];
    #pragma unroll
    for (int q = 0; q < BPC; q++) {
        cx[q] = sprep[q * 8 + 0]; cy[q] = sprep[q * 8 + 1];
        cz[q] = sprep[q * 8 + 2]; hx[q] = sprep[q * 8 + 3];
        hy[q] = sprep[q * 8 + 4]; hz[q] = sprep[q * 8 + 5];
        ca[q] = sprep[q * 8 + 6]; sa[q] = sprep[q * 8 + 7];
    }

    // this warp's point range: 256 points
    const int base_local = split * PPS + w * 256;          // batch-relative
    const float* pb = points + ((size_t)b * NPTS + base_local) * 3;

    int cnt[BPC];
    #pragma unroll
    for (int q = 0; q < BPC; q++) cnt[q] = 0;

    for (int j = 0; j < 8; j++) {
        const int i3 = (j * 32 + lane) * 3;
        const float x = pb[i3 + 0];
        const float y = pb[i3 + 1];
        const float z = pb[i3 + 2];
        #pragma unroll
        for (int q = 0; q < BPC; q++) {
            const float sx = __fsub_rn(x, cx[q]);
            const float sy = __fsub_rn(y, cy[q]);
            const float lx = __fsub_rn(__fmul_rn(sx, ca[q]), __fmul_rn(sy, sa[q]));
            const float ly = __fadd_rn(__fmul_rn(sx, sa[q]), __fmul_rn(sy, ca[q]));
            const float zd = __fsub_rn(z, cz[q]);
            // |lx|<hx  <=>  (lx>-hx && lx<hx) exactly (hx>0; NaN -> false)
            const bool m = (fabsf(zd) <= hz[q]) && (fabsf(lx) < hx[q]) && (fabsf(ly) < hy[q]);
            const unsigned ball = __ballot_sync(0xffffffffu, m);
            if (lane == 0) sball[q][w][j] = ball;
            cnt[q] += __popc(ball);
        }
    }
    if (lane == 0) {
        #pragma unroll
        for (int q = 0; q < BPC; q++) wtot[q][w] = cnt[q];
    }
    __syncthreads();

    // replay ballots with exclusive warp base -> ordered table entries
    const unsigned lt = (1u << lane) - 1u;
    #pragma unroll
    for (int q = 0; q < BPC; q++) {
        int run = 0;
        #pragma unroll
        for (int v = 0; v < 16; v++)
            if (v < w) run += wtot[q][v];
        int* tbl = g_table + (size_t)((bm0 + q) * PSPL + split) * SS;
        #pragma unroll
        for (int j = 0; j < 8; j++) {
            const unsigned ball = sball[q][w][j];
            const int pre = __popc(ball & lt);
            if (((ball >> lane) & 1u) && (run + pre) < SS)
                tbl[run + pre] = base_local + j * 32 + lane;
            run += __popc(ball);
        }
    }

    if (tid < BPC) {
        int tot = 0;
        #pragma unroll
        for (int v = 0; v < 16; v++) tot += wtot[tid][v];
        g_cnt[(bm0 + tid) * PSPL + split] = tot;
    }
}

// ---------------------------------------------------------------------------
// Kernel 2: gather pooled rows. TWO CTAs per box (256 threads, 8 warps each)
// for high occupancy (no min-blocks reg clamp -> up to 64 resident warps/SM).
// Each CTA resolves its 256 wrap-around indices once into smem, then each
// warp emits 32 consecutive rows, 4 rows per iteration, streaming stores.
// ---------------------------------------------------------------------------
__global__ __launch_bounds__(256) void roipool_gather_kernel(
    const float* __restrict__ points,   // (B, N, 3)
    const float* __restrict__ feats,    // (B, N, C)
    float* __restrict__ out,            // (B, M, S, 131)
    float* __restrict__ flags)          // (B, M)
{
    const int cid  = blockIdx.x;        // 0 .. 2*B*M-1
    const int bm   = cid >> 1;
    const int half = cid & 1;
    const int b    = bm >> 7;           // / MM
    const int tid  = threadIdx.x;
    const int lane = tid & 31;
    const int w    = tid >> 5;          // 0..7

    __shared__ int sidx[256];
    __shared__ int pf[4];
    __shared__ int scnt;

    if (tid == 0) {
        const int c0 = g_cnt[bm * PSPL + 0];
        const int c1 = g_cnt[bm * PSPL + 1];
        const int c2 = g_cnt[bm * PSPL + 2];
        const int c3 = g_cnt[bm * PSPL + 3];
        pf[0] = 0; pf[1] = c0; pf[2] = c0 + c1; pf[3] = c0 + c1 + c2;
        const int tot = c0 + c1 + c2 + c3;
        scnt = tot;
        if (half == 0) flags[bm] = (tot == 0) ? 1.0f : 0.0f;
    }
    __syncthreads();
    const int cnt = scnt;

    float* obox = out + (size_t)bm * SS * OUTF;
    const int rbase = half * 256;                 // first row of this CTA

    if (cnt == 0) {
        // zero this CTA's half slab: 256*131 floats, 16B-aligned start
        const float4 zz = make_float4(0.f, 0.f, 0.f, 0.f);
        float4* o4 = (float4*)(obox + (size_t)rbase * OUTF);
        for (int i = tid; i < 256 * OUTF / 4; i += 256) __stcs(&o4[i], zz);
        return;
    }

    // resolve wrap-around index for this thread's row
    {
        const int s = rbase + tid;
        const int j = s % cnt;
        const int p = (j >= pf[3]) ? 3 : (j >= pf[2]) ? 2 : (j >= pf[1]) ? 1 : 0;
        sidx[tid] = g_table[(size_t)(bm * PSPL + p) * SS + (j - pf[p])];
    }
    __syncthreads();

    const float* pbat = points + (size_t)b * NPTS * 3;
    const float* fbat = feats  + (size_t)b * NPTS * CF;

    // warp w handles rows rbase + [32w, 32w+32), 4 rows per iteration
    const int l0 = w * 32;                        // local row base
    for (int i = 0; i < 8; i++) {
        const int l = l0 + i * 4;
        float v[4][5];
        #pragma unroll
        for (int r = 0; r < 4; r++) {
            const int idx = sidx[l + r];
            const float* prow = pbat + (size_t)idx * 3;
            const float* frow = fbat + (size_t)idx * CF;
            v[r][0] = (lane < 3) ? prow[lane] : frow[lane - 3];
            v[r][1] = frow[lane + 29];
            v[r][2] = frow[lane + 61];
            v[r][3] = frow[lane + 93];
            v[r][4] = (lane < 3) ? frow[lane + 125] : 0.0f;
        }
        #pragma unroll
        for (int r = 0; r < 4; r++) {
            float* orow = obox + (size_t)(rbase + l + r) * OUTF;
            __stcs(&orow[lane],      v[r][0]);
            __stcs(&orow[lane + 32], v[r][1]);
            __stcs(&orow[lane + 64], v[r][2]);
            __stcs(&orow[lane + 96], v[r][3]);
            if (lane < 3) __stcs(&orow[lane + 128], v[r][4]);
        }
    }
}

// ---------------------------------------------------------------------------
extern "C" void kernel_launch(void* const* d_in, const int* in_sizes, int n_in,
                              void* d_out, int out_size)
{
    const float* points = (const float*)d_in[0];   // (B, N, 3)
    const float* feats  = (const float*)d_in[1];   // (B, N, C)
    const float* boxes  = (const float*)d_in[2];   // (B, M, 7)

    float* out   = (float*)d_out;
    float* flags = out + (size_t)BB * MM * SS * OUTF;  // empty flags appended

    roipool_mask_kernel<<<(BB * MM / BPC) * PSPL, 512>>>(points, boxes);
    roipool_gather_kernel<<<BB * MM * 2, 256>>>(points, feats, out, flags);
}

// round 5
// speedup vs baseline: 2.2686x; 1.0369x over previous
#include <cuda_runtime.h>
#include <cuda_bf16.h>
#include <math.h>

// Problem constants (fixed shapes for RoIPointPool3d_23845658427905)
#define BB   4
#define NPTS 16384
#define MM   128
#define CF   128
#define SS   512
#define OUTF (3 + CF)   // 131 floats per pooled row
#define BPC  4          // boxes per mask CTA
#define PSPL 4          // point-range splits per box group
#define PPS  (NPTS / PSPL)   // 4096 points per split

// Scratch (device globals — no allocation allowed)
__device__ int g_table[BB * MM * PSPL * SS]; // per (box, split): ordered in-box indices
__device__ int g_cnt[BB * MM * PSPL];        // per (box, split): in-box counts

// ---------------------------------------------------------------------------
// Kernel 1: fused box-prep (fp64 sincos, fast-math immune) + membership +
// ordered compaction. Grid: 128 box-quads x 4 point-splits = 512 CTAs,
// 512 threads. (Unchanged from R4 — proven correct, near issue floor.)
// ---------------------------------------------------------------------------
__global__ __launch_bounds__(512) void roipool_mask_kernel(
    const float* __restrict__ points,   // (B, N, 3)
    const float* __restrict__ boxes)    // (B, M, 7)
{
    const int split = blockIdx.x & (PSPL - 1);
    const int quad  = blockIdx.x >> 2;       // 0..127
    const int bm0   = quad * BPC;            // first box of the quad
    const int b     = bm0 >> 7;              // / MM

    __shared__ float    sprep[BPC * 8];      // cx, cy, czc, hx, hy, hz, ca, sa
    __shared__ unsigned sball[BPC][16][8];
    __shared__ int      wtot[BPC][16];

    const int tid  = threadIdx.x;
    const int lane = tid & 31;
    const int w    = tid >> 5;

    if (w == 0 && lane < BPC) {
        const int q = lane;
        const float* bx = boxes + (size_t)(bm0 + q) * 7;
        const float r0 = bx[0], r1 = bx[1], r2 = bx[2];
        const float r3 = bx[3], r4 = bx[4], r5 = bx[5], r6 = bx[6];
        double sv, cv;
        sincos(-(double)r6, &sv, &cv);
        float* o = sprep + q * 8;
        o[0] = r0;
        o[1] = r1;
        o[2] = __fadd_rn(r2, __fmul_rn(0.5f, r5));
        o[3] = __fmul_rn(0.5f, r3);
        o[4] = __fmul_rn(0.5f, r4);
        o[5] = __fmul_rn(0.5f, r5);
        o[6] = (float)cv;
        o[7] = (float)sv;
    }
    __syncthreads();

    float cx[BPC], cy[BPC], cz[BPC], hx[BPC], hy[BPC], hz[BPC], ca[BPC], sa[BPC];
    #pragma unroll
    for (int q = 0; q < BPC; q++) {
        cx[q] = sprep[q * 8 + 0]; cy[q] = sprep[q * 8 + 1];
        cz[q] = sprep[q * 8 + 2]; hx[q] = sprep[q * 8 + 3];
        hy[q] = sprep[q * 8 + 4]; hz[q] = sprep[q * 8 + 5];
        ca[q] = sprep[q * 8 + 6]; sa[q] = sprep[q * 8 + 7];
    }

    const int base_local = split * PPS + w * 256;          // batch-relative
    const float* pb = points + ((size_t)b * NPTS + base_local) * 3;

    int cnt[BPC];
    #pragma unroll
    for (int q = 0; q < BPC; q++) cnt[q] = 0;

    for (int j = 0; j < 8; j++) {
        const int i3 = (j * 32 + lane) * 3;
        const float x = pb[i3 + 0];
        const float y = pb[i3 + 1];
        const float z = pb[i3 + 2];
        #pragma unroll
        for (int q = 0; q < BPC; q++) {
            const float sx = __fsub_rn(x, cx[q]);
            const float sy = __fsub_rn(y, cy[q]);
            const float lx = __fsub_rn(__fmul_rn(sx, ca[q]), __fmul_rn(sy, sa[q]));
            const float ly = __fadd_rn(__fmul_rn(sx, sa[q]), __fmul_rn(sy, ca[q]));
            const float zd = __fsub_rn(z, cz[q]);
            const bool m = (fabsf(zd) <= hz[q]) && (fabsf(lx) < hx[q]) && (fabsf(ly) < hy[q]);
            const unsigned ball = __ballot_sync(0xffffffffu, m);
            if (lane == 0) sball[q][w][j] = ball;
            cnt[q] += __popc(ball);
        }
    }
    if (lane == 0) {
        #pragma unroll
        for (int q = 0; q < BPC; q++) wtot[q][w] = cnt[q];
    }
    __syncthreads();

    const unsigned lt = (1u << lane) - 1u;
    #pragma unroll
    for (int q = 0; q < BPC; q++) {
        int run = 0;
        #pragma unroll
        for (int v = 0; v < 16; v++)
            if (v < w) run += wtot[q][v];
        int* tbl = g_table + (size_t)((bm0 + q) * PSPL + split) * SS;
        #pragma unroll
        for (int j = 0; j < 8; j++) {
            const unsigned ball = sball[q][w][j];
            const int pre = __popc(ball & lt);
            if (((ball >> lane) & 1u) && (run + pre) < SS)
                tbl[run + pre] = base_local + j * 32 + lane;
            run += __popc(ball);
        }
    }

    if (tid < BPC) {
        int tot = 0;
        #pragma unroll
        for (int v = 0; v < 16; v++) tot += wtot[tid][v];
        g_cnt[(bm0 + tid) * PSPL + split] = tot;
    }
}

// ---------------------------------------------------------------------------
// Kernel 2: gather pooled rows — ALIGNED loads + register rotate-by-3.
// Feature rows are 512B-aligned, so v[k] = frow[lane + 32k] is exactly one
// 128B line per load (4 wavefronts instead of 10 for shifted addressing).
// The +3-word output shift is done in registers with one shuffle per segment:
//   r[k][lane] = v[k][(lane-3) mod 32]
//   out[lane     ] = lane<3 ? point[lane] : r[0]
//   out[lane+32k ] = lane>=3 ? r[k] : r[k-1]        (k = 1..3)
//   out[128+lane ] = r[3]   (lane<3: v[3][29+lane] = feat col 125+lane)
// TWO CTAs per box, 256 threads, 4 rows in flight per warp, streaming stores.
// ---------------------------------------------------------------------------
__global__ __launch_bounds__(256) void roipool_gather_kernel(
    const float* __restrict__ points,   // (B, N, 3)
    const float* __restrict__ feats,    // (B, N, C)
    float* __restrict__ out,            // (B, M, S, 131)
    float* __restrict__ flags)          // (B, M)
{
    const int cid  = blockIdx.x;        // 0 .. 2*B*M-1
    const int bm   = cid >> 1;
    const int half = cid & 1;
    const int b    = bm >> 7;           // / MM
    const int tid  = threadIdx.x;
    const int lane = tid & 31;
    const int w    = tid >> 5;          // 0..7

    __shared__ int sidx[256];
    __shared__ int pf[4];
    __shared__ int scnt;

    if (tid == 0) {
        const int c0 = g_cnt[bm * PSPL + 0];
        const int c1 = g_cnt[bm * PSPL + 1];
        const int c2 = g_cnt[bm * PSPL + 2];
        const int c3 = g_cnt[bm * PSPL + 3];
        pf[0] = 0; pf[1] = c0; pf[2] = c0 + c1; pf[3] = c0 + c1 + c2;
        const int tot = c0 + c1 + c2 + c3;
        scnt = tot;
        if (half == 0) flags[bm] = (tot == 0) ? 1.0f : 0.0f;
    }
    __syncthreads();
    const int cnt = scnt;

    float* obox = out + (size_t)bm * SS * OUTF;
    const int rbase = half * 256;                 // first row of this CTA

    if (cnt == 0) {
        const float4 zz = make_float4(0.f, 0.f, 0.f, 0.f);
        float4* o4 = (float4*)(obox + (size_t)rbase * OUTF);
        for (int i = tid; i < 256 * OUTF / 4; i += 256) __stcs(&o4[i], zz);
        return;
    }

    // resolve wrap-around index for this thread's row
    {
        const int s = rbase + tid;
        const int j = s % cnt;
        const int p = (j >= pf[3]) ? 3 : (j >= pf[2]) ? 2 : (j >= pf[1]) ? 1 : 0;
        sidx[tid] = g_table[(size_t)(bm * PSPL + p) * SS + (j - pf[p])];
    }
    __syncthreads();

    const float* pbat = points + (size_t)b * NPTS * 3;
    const float* fbat = feats  + (size_t)b * NPTS * CF;

    const int srcLane = (lane + 29) & 31;         // (lane - 3) mod 32
    const bool lo3 = (lane < 3);

    // warp w handles rows rbase + [32w, 32w+32), 4 rows per iteration
    const int l0 = w * 32;                        // local row base
    for (int i = 0; i < 8; i++) {
        const int l = l0 + i * 4;
        float v[4][4];                            // aligned feature segments
        float pv[4];                              // point value (lanes 0-2)
        #pragma unroll
        for (int r = 0; r < 4; r++) {
            const int idx = sidx[l + r];
            const float* frow = fbat + (size_t)idx * CF;
            const float* prow = pbat + (size_t)idx * 3;
            v[r][0] = frow[lane];
            v[r][1] = frow[lane + 32];
            v[r][2] = frow[lane + 64];
            v[r][3] = frow[lane + 96];
            pv[r]   = lo3 ? prow[lane] : 0.0f;
        }
        #pragma unroll
        for (int r = 0; r < 4; r++) {
            const float r0 = __shfl_sync(0xffffffffu, v[r][0], srcLane);
            const float r1 = __shfl_sync(0xffffffffu, v[r][1], srcLane);
            const float r2 = __shfl_sync(0xffffffffu, v[r][2], srcLane);
            const float r3 = __shfl_sync(0xffffffffu, v[r][3], srcLane);
            const float s0 = lo3 ? pv[r] : r0;
            const float s1 = lo3 ? r0 : r1;
            const float s2 = lo3 ? r1 : r2;
            const float s3 = lo3 ? r2 : r3;
            float* orow = obox + (size_t)(rbase + l + r) * OUTF;
            __stcs(&orow[lane],      s0);
            __stcs(&orow[lane + 32], s1);
            __stcs(&orow[lane + 64], s2);
            __stcs(&orow[lane + 96], s3);
            if (lo3) __stcs(&orow[lane + 128], r3);
        }
    }
}

// ---------------------------------------------------------------------------
extern "C" void kernel_launch(void* const* d_in, const int* in_sizes, int n_in,
                              void* d_out, int out_size)
{
    const float* points = (const float*)d_in[0];   // (B, N, 3)
    const float* feats  = (const float*)d_in[1];   // (B, N, C)
    const float* boxes  = (const float*)d_in[2];   // (B, M, 7)

    float* out   = (float*)d_out;
    float* flags = out + (size_t)BB * MM * SS * OUTF;  // empty flags appended

    roipool_mask_kernel<<<(BB * MM / BPC) * PSPL, 512>>>(points, boxes);
    roipool_gather_kernel<<<BB * MM * 2, 256>>>(points, feats, out, flags);
}